// round 8
// baseline (speedup 1.0000x reference)
#include <cuda_runtime.h>
#include <cstdint>

// out[b,s,:] = x[b,s,:] + combined[s,:]  (combined batch-invariant, from 3 PE tables)
// x: [8, 16384, 512] fp32 -> 256 MiB read + 256 MiB write, pure HBM streaming.
// Shape: 256-thread block handles TWO consecutive s-positions (grid = S/2 = 8192).
//   - thread t: sub-row r = t>>7 (0/1), lane = t&127 over D/4.
//   - x loads issued first (independent), searches/PE gathers overlap them.

#define B_CONST 8
#define D4 128            // D/4 = 512/4
#define MAX_PIXELS 900
#define ROWS_PER_BLK 2

__global__ __launch_bounds__(256)
void pe_add_kernel(const float4* __restrict__ x,
                   const float4* __restrict__ pix_pe,
                   const float4* __restrict__ grd_pe,
                   const float4* __restrict__ pr_pe,
                   const int*    __restrict__ g_starts,
                   const int*    __restrict__ g_lens,
                   const int*    __restrict__ p_starts,
                   const int*    __restrict__ p_lens,
                   int n_grids, int n_pairs, int n_pairs_pe_rows,
                   int S,
                   float4* __restrict__ out)
{
    const int lane = threadIdx.x & (D4 - 1);        // 0..127 over D
    const int r    = threadIdx.x >> 7;              // 0..1 sub-row
    const int s    = blockIdx.x * ROWS_PER_BLK + r;

    // ---- issue the big streaming loads first (independent of index math) ----
    const size_t row = (size_t)s * D4 + lane;
    const size_t bstride = (size_t)S * D4;
    float4 v[B_CONST];
#pragma unroll
    for (int b = 0; b < B_CONST; ++b)
        v[b] = x[row + (size_t)b * bstride];

    // ---- searchsorted(grid_starts, s, 'right') - 1 (overlapped with x loads) ----
    int lo = 0, hi = n_grids;
    while (lo < hi) {
        int mid = (lo + hi) >> 1;
        if (g_starts[mid] <= s) lo = mid + 1; else hi = mid;
    }
    const int gid  = lo - 1;
    const int goff = s - g_starts[gid];
    const bool gmask = (goff < g_lens[gid]);
    int goffc = goff; if (goffc < 0) goffc = 0; if (goffc > MAX_PIXELS - 1) goffc = MAX_PIXELS - 1;

    // ---- searchsorted(pair_starts, s, 'right') - 1 ----
    lo = 0; hi = n_pairs;
    while (lo < hi) {
        int mid = (lo + hi) >> 1;
        if (p_starts[mid] <= s) lo = mid + 1; else hi = mid;
    }
    const int pid  = lo - 1;
    const int poff = s - p_starts[pid];
    const bool pmask = (poff < p_lens[pid]);
    int pidc = pid; if (pidc < 0) pidc = 0; if (pidc > n_pairs_pe_rows - 1) pidc = n_pairs_pe_rows - 1;

    // ---- combined[s, lane*4..lane*4+3] in registers (PE tables L1/L2 resident) ----
    float4 comb = make_float4(0.f, 0.f, 0.f, 0.f);
    if (gmask) {
        float4 a = __ldg(&pix_pe[(size_t)goffc * D4 + lane]);
        float4 b = __ldg(&grd_pe[(size_t)(gid & 1) * D4 + lane]);
        comb.x = a.x + b.x; comb.y = a.y + b.y; comb.z = a.z + b.z; comb.w = a.w + b.w;
    }
    if (pmask) {
        float4 c = __ldg(&pr_pe[(size_t)pidc * D4 + lane]);
        comb.x += c.x; comb.y += c.y; comb.z += c.z; comb.w += c.w;
    }

    // ---- add + store ----
#pragma unroll
    for (int b = 0; b < B_CONST; ++b) {
        v[b].x += comb.x; v[b].y += comb.y; v[b].z += comb.z; v[b].w += comb.w;
        out[row + (size_t)b * bstride] = v[b];
    }
}

extern "C" void kernel_launch(void* const* d_in, const int* in_sizes, int n_in,
                              void* d_out, int out_size)
{
    const float* x        = (const float*)d_in[0];
    const float* pix_pe   = (const float*)d_in[1];
    const float* grd_pe   = (const float*)d_in[2];
    const float* pr_pe    = (const float*)d_in[3];
    const int*   g_starts = (const int*)d_in[4];
    const int*   g_lens   = (const int*)d_in[5];
    const int*   p_starts = (const int*)d_in[6];
    const int*   p_lens   = (const int*)d_in[7];

    const int D = in_sizes[2] / 2;            // grids_pe is [2, D]
    const int n_grids = in_sizes[4];
    const int n_pairs = in_sizes[6];
    const int n_pairs_pe_rows = in_sizes[3] / D;
    const int S = out_size / (B_CONST * D);   // 16384

    pe_add_kernel<<<S / ROWS_PER_BLK, 256>>>(
        (const float4*)x, (const float4*)pix_pe, (const float4*)grd_pe, (const float4*)pr_pe,
        g_starts, g_lens, p_starts, p_lens,
        n_grids, n_pairs, n_pairs_pe_rows, S,
        (float4*)d_out);
}

// round 11
// speedup vs baseline: 1.0523x; 1.0523x over previous
#include <cuda_runtime.h>
#include <cstdint>

// out[b,s,:] = x[b,s,:] + combined[s,:]  (combined batch-invariant, from 3 PE tables)
// x: [8, 16384, 512] fp32 -> 256 MiB read + 256 MiB write, pure HBM streaming.
// Shape (best-known): one block per s-position, 16384 blocks x 128 threads.
// This round: route the touch-once x/out streams around L1 (.cg), keep L1 for
// the reused PE-table gathers.

#define B_CONST 8
#define D4 128            // D/4 = 512/4
#define MAX_PIXELS 900

__global__ __launch_bounds__(128)
void pe_add_kernel(const float4* __restrict__ x,
                   const float4* __restrict__ pix_pe,
                   const float4* __restrict__ grd_pe,
                   const float4* __restrict__ pr_pe,
                   const int*    __restrict__ g_starts,
                   const int*    __restrict__ g_lens,
                   const int*    __restrict__ p_starts,
                   const int*    __restrict__ p_lens,
                   int n_grids, int n_pairs, int n_pairs_pe_rows,
                   int S,
                   float4* __restrict__ out)
{
    const int s = blockIdx.x;
    const int t = threadIdx.x;   // 0..127 -> float4 lane over D

    // ---- searchsorted(grid_starts, s, 'right') - 1 ----
    int lo = 0, hi = n_grids;
    while (lo < hi) {
        int mid = (lo + hi) >> 1;
        if (g_starts[mid] <= s) lo = mid + 1; else hi = mid;
    }
    const int gid  = lo - 1;
    const int goff = s - g_starts[gid];
    const bool gmask = (goff < g_lens[gid]);
    int goffc = goff; if (goffc < 0) goffc = 0; if (goffc > MAX_PIXELS - 1) goffc = MAX_PIXELS - 1;

    // ---- searchsorted(pair_starts, s, 'right') - 1 ----
    lo = 0; hi = n_pairs;
    while (lo < hi) {
        int mid = (lo + hi) >> 1;
        if (p_starts[mid] <= s) lo = mid + 1; else hi = mid;
    }
    const int pid  = lo - 1;
    const int poff = s - p_starts[pid];
    const bool pmask = (poff < p_lens[pid]);
    int pidc = pid; if (pidc < 0) pidc = 0; if (pidc > n_pairs_pe_rows - 1) pidc = n_pairs_pe_rows - 1;

    // ---- combined[s, t*4..t*4+3] in registers (PE tables: L1-cached gathers) ----
    float4 comb = make_float4(0.f, 0.f, 0.f, 0.f);
    if (gmask) {
        float4 a = __ldg(&pix_pe[(size_t)goffc * D4 + t]);
        float4 b = __ldg(&grd_pe[(size_t)(gid & 1) * D4 + t]);
        comb.x = a.x + b.x; comb.y = a.y + b.y; comb.z = a.z + b.z; comb.w = a.w + b.w;
    }
    if (pmask) {
        float4 c = __ldg(&pr_pe[(size_t)pidc * D4 + t]);
        comb.x += c.x; comb.y += c.y; comb.z += c.z; comb.w += c.w;
    }

    // ---- per-batch load(.cg) + add + store(.cg): L1-bypass for touch-once data ----
    const size_t row = (size_t)s * D4 + t;
    const size_t bstride = (size_t)S * D4;
#pragma unroll
    for (int b = 0; b < B_CONST; ++b) {
        float4 v = __ldcg(&x[row + (size_t)b * bstride]);
        v.x += comb.x; v.y += comb.y; v.z += comb.z; v.w += comb.w;
        __stcg(&out[row + (size_t)b * bstride], v);
    }
}

extern "C" void kernel_launch(void* const* d_in, const int* in_sizes, int n_in,
                              void* d_out, int out_size)
{
    const float* x        = (const float*)d_in[0];
    const float* pix_pe   = (const float*)d_in[1];
    const float* grd_pe   = (const float*)d_in[2];
    const float* pr_pe    = (const float*)d_in[3];
    const int*   g_starts = (const int*)d_in[4];
    const int*   g_lens   = (const int*)d_in[5];
    const int*   p_starts = (const int*)d_in[6];
    const int*   p_lens   = (const int*)d_in[7];

    const int D = in_sizes[2] / 2;            // grids_pe is [2, D]
    const int n_grids = in_sizes[4];
    const int n_pairs = in_sizes[6];
    const int n_pairs_pe_rows = in_sizes[3] / D;
    const int S = out_size / (B_CONST * D);   // 16384

    pe_add_kernel<<<S, 128>>>(
        (const float4*)x, (const float4*)pix_pe, (const float4*)grd_pe, (const float4*)pr_pe,
        g_starts, g_lens, p_starts, p_lens,
        n_grids, n_pairs, n_pairs_pe_rows, S,
        (float4*)d_out);
}